// round 15
// baseline (speedup 1.0000x reference)
#include <cuda_runtime.h>
#include <cstddef>

#define NALGOS 64
#define NTASKS 1024
#define LXN    512
#define TSTEPS 513
#define L2E    1.44269504088896f

__device__ float g_GT[LXN * LXN];          // GT[s][t] = tm[lx[t]][lx[s]]
__device__ float g_dvec[LXN];              // -log2e / diff[lx[s]]
__device__ float g_Gq[132 * 4096];         // Gq[tq][j][k] = tm[lx[4tq+k]][j] (+pad)

// ---------------------------------------------------------------------------
__global__ void prep_kernel(const int*   __restrict__ lx,
                            const float* __restrict__ tm,
                            const float* __restrict__ diff)
{
    const int s  = blockIdx.x;
    const int t  = threadIdx.x;
    g_GT[s * LXN + t] = tm[(size_t)lx[t] * NTASKS + lx[s]];
    if (s == 0) g_dvec[t] = -L2E / diff[lx[t]];
}

__global__ void prep2_kernel(const int* __restrict__ lx,
                             const float* __restrict__ tm)
{
    const int tq = blockIdx.x;      // 0..127
    const int j  = threadIdx.x;     // 0..1023
    const int t  = tq * 4;
    float4 v;
    v.x = tm[(size_t)lx[t + 0] * NTASKS + j];
    v.y = tm[(size_t)lx[t + 1] * NTASKS + j];
    v.z = tm[(size_t)lx[t + 2] * NTASKS + j];
    v.w = tm[(size_t)lx[t + 3] * NTASKS + j];
    ((float4*)g_Gq)[tq * 1024 + j] = v;
}

// ---------------------------------------------------------------------------
// Fused kernel. Grid (4 j-quarters, 16 algo groups) x 640 threads.
//   Warps 0-3:  leaders — serial coef chain for algo 4p+w (concurrent,
//               independent; shared Gd tile since GT/dvec are algo-free).
//   Warps 4-19: followers — (a) triangular batch updates + handoff for all
//               4 algos (slot block fw = w-4), Gd tile staging, gt prefetch;
//               (b) DURING leader block m, run phase-2 output chains for
//               coef block m-1: 2 chains/thread (algos 2g,2g+1 at one j ->
//               one shared Gq column stream), transposed-tile coalesced STG.
// Phase 2 thus hides entirely under the serial chain.
// ---------------------------------------------------------------------------
#define FTHREADS 640

__global__ void __launch_bounds__(FTHREADS, 1)
fused_kernel(const float* __restrict__ eff_g,
             const float* __restrict__ mem_g,
             const float* __restrict__ boost_g,
             const float* __restrict__ diff,
             float*       __restrict__ out)
{
    extern __shared__ float tiles[];                  // [16][2][32*33]
    __shared__ float Gd_sh[32][33];
    __shared__ __align__(16) float coef_sh[4][LXN];
    __shared__ __align__(16) float cmul_sh[4][32];    // coef*mem^(31-i), prev block
    __shared__ __align__(16) float mp_sh[4][32];      // mem^(31-i)
    __shared__ float dvec_sh[LXN];
    __shared__ float handoff[4][32];
    __shared__ float mem32_sh[4];

    const int tid   = threadIdx.x;
    const int w     = tid >> 5;
    const int lane  = tid & 31;
    const int p     = blockIdx.y;          // algo group
    const int h     = blockIdx.x;          // j quarter
    const int abase = p * 4;

    if (tid < LXN) dvec_sh[tid] = g_dvec[tid];
    if (tid < 4) {
        const float mm = mem_g[abase + tid];
        float pw = 1.0f;
        for (int i = 31; i >= 0; --i) { mp_sh[tid][i] = pw; pw *= mm; }
        mem32_sh[tid] = pw;
    }
    for (int i = tid; i < 1024; i += FTHREADS) {      // Gd tile block 0
        const int r_ = i >> 5, k_ = i & 31;
        Gd_sh[r_][k_] = g_GT[r_ * LXN + k_] * g_dvec[r_];
    }

    // ---- leader state ----
    float l_eff = 0.f, l_mem = 0.f, l_c0 = 0.f, l_c1 = 0.f;
    if (w < 4) {
        l_eff = eff_g[abase + w];
        l_mem = mem_g[abase + w];
        const float bo = boost_g[abase + w];
        l_c0 = l_eff - bo;
        l_c1 = 2.0f * bo;
    }

    // ---- follower state ----
    const int fw   = w - 4;                 // 0..15 (followers only)
    const int slot = fw * 32 + lane;
    float res4[4] = {0.f, 0.f, 0.f, 0.f};   // triangular slot states (per algo)
    float4 gt[8];                           // raw G chunk (shared across algos)
    float tile_reg[2];

    // phase-2 chain state
    int   g0 = 0, j = 0;
    float hid = 0.f, memA = 0.f, memB = 0.f, resA = 0.f, resB = 0.f;
    float4 ring[2];
    float *tileA = nullptr, *tileB = nullptr;
    const float4* __restrict__ Gq4 = (const float4*)g_Gq;

    if (w >= 4) {
        const float4* gp = (const float4*)(g_GT + (size_t)slot * LXN);
        #pragma unroll
        for (int q = 0; q < 8; ++q) gt[q] = gp[q];

        const int ft = tid - 128;           // 0..511
        g0   = 2 * (ft >> 8);               // 0 or 2
        j    = h * 256 + (ft & 255);
        hid  = 0.5f / diff[j];              // 2*sigmoid(x/d)-1 = tanh(x/2d)
        memA = mem_g[abase + g0];
        memB = mem_g[abase + g0 + 1];
        ring[0] = Gq4[0 * 1024 + j];
        ring[1] = Gq4[1 * 1024 + j];
        out[((size_t)(abase + g0)     * NTASKS + j) * TSTEPS] = 0.0f;  // t=0
        out[((size_t)(abase + g0 + 1) * NTASKS + j) * TSTEPS] = 0.0f;
        tileA = tiles + fw * (2 * 32 * 33);
        tileB = tileA + 32 * 33;
    }
    __syncthreads();

    for (int m = 0; m < 16; ++m) {
        // ---------- pre-block (serial region) ----------
        if (m > 0) {
            if (w >= 4) {
                {   // stage Gd tile m from prefetched regs
                    int q = 0;
                    for (int i = tid - 128; i < 1024; i += 512, ++q)
                        Gd_sh[i >> 5][i & 31] = tile_reg[q];
                }
                if (fw >= m) {              // apply coef block m-1 to my slot
                    const float* gf = (const float*)gt;
                    #pragma unroll
                    for (int g = 0; g < 4; ++g) {
                        const float4* cm4 = (const float4*)cmul_sh[g];
                        float s0 = 0.f, s1 = 0.f, s2 = 0.f, s3 = 0.f;
                        #pragma unroll
                        for (int i = 0; i < 8; ++i) {
                            const float4 cm = cm4[i];
                            s0 = fmaf(gf[4 * i + 0], cm.x, s0);
                            s1 = fmaf(gf[4 * i + 1], cm.y, s1);
                            s2 = fmaf(gf[4 * i + 2], cm.z, s2);
                            s3 = fmaf(gf[4 * i + 3], cm.w, s3);
                        }
                        res4[g] = fmaf(res4[g], mem32_sh[g], (s0 + s1) + (s2 + s3));
                    }
                }
                if (fw == m) {
                    #pragma unroll
                    for (int g = 0; g < 4; ++g)
                        handoff[g][lane] = res4[g] * dvec_sh[slot];
                }
            }
        } else {
            if (w == 4) {
                #pragma unroll
                for (int g = 0; g < 4; ++g) handoff[g][lane] = 0.0f;
            }
        }
        __syncthreads();

        // ---------- parallel region ----------
        if (w < 4) {
            // ===== leader: serial block m (R12-proven code, per-algo w) =====
            float bd = handoff[w][lane];
            const int tb = m * 32;
            const float mem2 = l_mem * l_mem;
            float mycoef = 0.0f;

            float x  = __shfl_sync(0xffffffffu, bd, 0);
            float b1 = __shfl_sync(0xffffffffu, bd, 1);
            const float g10 = Gd_sh[1][0];
            float Pn  = fmaf(b1, l_mem, g10 * l_c0);
            float B2n = g10 * l_c1;

            float e, r;
            #pragma unroll
            for (int k = 0; k < 32; ++k) {
                float S = 0.0f;
                if (k < 30) S = __shfl_sync(0xffffffffu, bd, k + 2);
                asm("ex2.approx.f32 %0, %1;" : "=f"(e) : "f"(x));
                asm("rcp.approx.f32 %0, %1;" : "=f"(r) : "f"(e + 1.0f));
                const float coef = fmaf(l_c1, r, l_c0);
                if (lane == 0) coef_sh[w][tb + k] = coef;
                if (lane == k) mycoef = coef;

                if (k < 31) x = fmaf(B2n, r, Pn);
                if (k < 30) {
                    const float g1 = Gd_sh[k + 2][k];
                    const float g2 = Gd_sh[k + 2][k + 1];
                    const float A  = fmaf(S, mem2, fmaf(g1, l_mem, g2) * l_c0);
                    Pn  = fmaf(g1 * l_mem * l_c1, r, A);
                    B2n = g2 * l_c1;
                }
                if (lane > k) bd = fmaf(bd, l_mem, Gd_sh[lane][k] * coef);
            }
            cmul_sh[w][lane] = mycoef * mp_sh[w][lane];   // for next batch-apply
        } else {
            // ===== followers =====
            if (fw > m) {       // prefetch raw-G chunk for block-m coefs
                const float4* gp = (const float4*)(g_GT + (size_t)slot * LXN + m * 32);
                #pragma unroll
                for (int q = 0; q < 8; ++q) gt[q] = gp[q];
            }
            if (m < 15) {       // prefetch next Gd diagonal tile (dvec-scaled)
                const int base = 32 * (m + 1);
                int q = 0;
                for (int i = tid - 128; i < 1024; i += 512, ++q) {
                    const int s_ = base + (i >> 5);
                    tile_reg[q] = g_GT[(size_t)s_ * LXN + base + (i & 31)] * dvec_sh[s_];
                }
            }
            if (m >= 1) {
                // phase-2 tile for coef block mb = m-1 (final since last sync)
                const int mb = m - 1;
                #pragma unroll
                for (int q = 0; q < 8; ++q) {
                    const int tq = mb * 8 + q;
                    const float4 cur = ring[q & 1];
                    ring[q & 1] = Gq4[(tq + 2) * 1024 + j];
                    const float4 cfA = *(const float4*)&coef_sh[g0][tq << 2];
                    const float4 cfB = *(const float4*)&coef_sh[g0 + 1][tq << 2];
                    float s;
                    resA = fmaf(resA, memA, cur.x * cfA.x);
                    asm("tanh.approx.f32 %0, %1;" : "=f"(s) : "f"(resA * hid));
                    tileA[(q * 4 + 0) * 33 + lane] = s;
                    resB = fmaf(resB, memB, cur.x * cfB.x);
                    asm("tanh.approx.f32 %0, %1;" : "=f"(s) : "f"(resB * hid));
                    tileB[(q * 4 + 0) * 33 + lane] = s;
                    resA = fmaf(resA, memA, cur.y * cfA.y);
                    asm("tanh.approx.f32 %0, %1;" : "=f"(s) : "f"(resA * hid));
                    tileA[(q * 4 + 1) * 33 + lane] = s;
                    resB = fmaf(resB, memB, cur.y * cfB.y);
                    asm("tanh.approx.f32 %0, %1;" : "=f"(s) : "f"(resB * hid));
                    tileB[(q * 4 + 1) * 33 + lane] = s;
                    resA = fmaf(resA, memA, cur.z * cfA.z);
                    asm("tanh.approx.f32 %0, %1;" : "=f"(s) : "f"(resA * hid));
                    tileA[(q * 4 + 2) * 33 + lane] = s;
                    resB = fmaf(resB, memB, cur.z * cfB.z);
                    asm("tanh.approx.f32 %0, %1;" : "=f"(s) : "f"(resB * hid));
                    tileB[(q * 4 + 2) * 33 + lane] = s;
                    resA = fmaf(resA, memA, cur.w * cfA.w);
                    asm("tanh.approx.f32 %0, %1;" : "=f"(s) : "f"(resA * hid));
                    tileA[(q * 4 + 3) * 33 + lane] = s;
                    resB = fmaf(resB, memB, cur.w * cfB.w);
                    asm("tanh.approx.f32 %0, %1;" : "=f"(s) : "f"(resB * hid));
                    tileB[(q * 4 + 3) * 33 + lane] = s;
                }
                __syncwarp();
                const int jb = h * 256 + ((fw & 7) << 5);
                #pragma unroll 2
                for (int i = 0; i < 32; ++i) {
                    const size_t tcol = (size_t)(1 + (mb << 5) + lane);
                    out[((size_t)(abase + g0)     * NTASKS + jb + i) * TSTEPS + tcol]
                        = tileA[lane * 33 + i];
                    out[((size_t)(abase + g0 + 1) * NTASKS + jb + i) * TSTEPS + tcol]
                        = tileB[lane * 33 + i];
                }
                __syncwarp();
            }
        }
        __syncthreads();
    }

    // ---------- epilogue: phase-2 tile for final coef block 15 ----------
    if (w >= 4) {
        const int mb = 15;
        #pragma unroll
        for (int q = 0; q < 8; ++q) {
            const int tq = mb * 8 + q;
            const float4 cur = ring[q & 1];
            if (q < 6) ring[q & 1] = Gq4[(tq + 2) * 1024 + j];
            const float4 cfA = *(const float4*)&coef_sh[g0][tq << 2];
            const float4 cfB = *(const float4*)&coef_sh[g0 + 1][tq << 2];
            float s;
            resA = fmaf(resA, memA, cur.x * cfA.x);
            asm("tanh.approx.f32 %0, %1;" : "=f"(s) : "f"(resA * hid));
            tileA[(q * 4 + 0) * 33 + lane] = s;
            resB = fmaf(resB, memB, cur.x * cfB.x);
            asm("tanh.approx.f32 %0, %1;" : "=f"(s) : "f"(resB * hid));
            tileB[(q * 4 + 0) * 33 + lane] = s;
            resA = fmaf(resA, memA, cur.y * cfA.y);
            asm("tanh.approx.f32 %0, %1;" : "=f"(s) : "f"(resA * hid));
            tileA[(q * 4 + 1) * 33 + lane] = s;
            resB = fmaf(resB, memB, cur.y * cfB.y);
            asm("tanh.approx.f32 %0, %1;" : "=f"(s) : "f"(resB * hid));
            tileB[(q * 4 + 1) * 33 + lane] = s;
            resA = fmaf(resA, memA, cur.z * cfA.z);
            asm("tanh.approx.f32 %0, %1;" : "=f"(s) : "f"(resA * hid));
            tileA[(q * 4 + 2) * 33 + lane] = s;
            resB = fmaf(resB, memB, cur.z * cfB.z);
            asm("tanh.approx.f32 %0, %1;" : "=f"(s) : "f"(resB * hid));
            tileB[(q * 4 + 2) * 33 + lane] = s;
            resA = fmaf(resA, memA, cur.w * cfA.w);
            asm("tanh.approx.f32 %0, %1;" : "=f"(s) : "f"(resA * hid));
            tileA[(q * 4 + 3) * 33 + lane] = s;
            resB = fmaf(resB, memB, cur.w * cfB.w);
            asm("tanh.approx.f32 %0, %1;" : "=f"(s) : "f"(resB * hid));
            tileB[(q * 4 + 3) * 33 + lane] = s;
        }
        __syncwarp();
        const int jb = h * 256 + ((fw & 7) << 5);
        #pragma unroll 2
        for (int i = 0; i < 32; ++i) {
            const size_t tcol = (size_t)(1 + (mb << 5) + lane);
            out[((size_t)(abase + g0)     * NTASKS + jb + i) * TSTEPS + tcol]
                = tileA[lane * 33 + i];
            out[((size_t)(abase + g0 + 1) * NTASKS + jb + i) * TSTEPS + tcol]
                = tileB[lane * 33 + i];
        }
    }
}

extern "C" void kernel_launch(void* const* d_in, const int* in_sizes, int n_in,
                              void* d_out, int out_size)
{
    const int*   lx    = (const int*)  d_in[0];
    const float* tm    = (const float*)d_in[1];
    const float* diff  = (const float*)d_in[2];
    const float* eff   = (const float*)d_in[3];
    const float* mem   = (const float*)d_in[4];
    const float* boost = (const float*)d_in[5];
    float*       out   = (float*)d_out;

    const int tiles_bytes = 16 * 2 * 32 * 33 * (int)sizeof(float);  // 135,168
    cudaFuncSetAttribute(fused_kernel,
                         cudaFuncAttributeMaxDynamicSharedMemorySize, tiles_bytes);

    prep_kernel<<<LXN, LXN>>>(lx, tm, diff);
    prep2_kernel<<<128, 1024>>>(lx, tm);
    dim3 grid(4, 16);
    fused_kernel<<<grid, FTHREADS, tiles_bytes>>>(eff, mem, boost, diff, out);
}